// round 15
// baseline (speedup 1.0000x reference)
#include <cuda_runtime.h>
#include <cuda_fp16.h>
#include <cstdint>
#include <math.h>

#define B_SZ 32
#define T_SZ 2048
#define D_SZ 1024
#define U_SZ 1024
#define NPASS 16
#define CSPLIT 8

typedef unsigned long long u64;

// ---------------- static device scratch (no runtime allocation) -------------
__device__ float g_A[B_SZ * U_SZ];               // q@W1 + b1 + b2
__device__ float g_spart[NPASS * B_SZ * T_SZ];   // per-pass partial scores
__device__ float g_cpart[CSPLIT * B_SZ * D_SZ];  // context partials
__device__ __half g_W2t[U_SZ * D_SZ];            // W2^T fp16 [u][d]
__device__ __half g_vh[67108864];                // values as fp16 (B*T*D)

// ---------------- PTX helpers ----------------------------------------------
__device__ __forceinline__ uint32_t smem_u32(const void* p) {
    uint32_t a;
    asm("{ .reg .u64 t; cvta.to.shared.u64 t, %1; cvt.u32.u64 %0, t; }"
        : "=r"(a) : "l"(p));
    return a;
}
__device__ __forceinline__ float tanh_approx(float x) {
    float y;
    asm("tanh.approx.f32 %0, %1;" : "=f"(y) : "f"(x));
    return y;
}
#define CP16(s, g) \
    asm volatile("cp.async.cg.shared.global [%0], [%1], 16;" :: "r"(s), "l"(g))
#define CP_COMMIT() asm volatile("cp.async.commit_group;" ::: "memory")
#define CP_WAIT(n) asm volatile("cp.async.wait_group %0;" :: "n"(n) : "memory")
#define LDSM4(R0, R1, R2, R3, A) \
    asm volatile("ldmatrix.sync.aligned.m8n8.x4.shared.b16 {%0,%1,%2,%3}, [%4];" \
                 : "=r"(R0), "=r"(R1), "=r"(R2), "=r"(R3) : "r"(A))
#define MMA_F16(d, a, b0, b1)                                               \
    asm volatile(                                                           \
        "mma.sync.aligned.m16n8k16.row.col.f32.f16.f16.f32 "                \
        "{%0,%1,%2,%3}, {%4,%5,%6,%7}, {%8,%9}, {%0,%1,%2,%3};"             \
        : "+f"((d)[0]), "+f"((d)[1]), "+f"((d)[2]), "+f"((d)[3])            \
        : "r"((a)[0]), "r"((a)[1]), "r"((a)[2]), "r"((a)[3]),               \
          "r"(b0), "r"(b1))

// ---------------------------------------------------------------------------
// Kernel P0: values fp32 -> fp16 (one uint4 = 8 halves per thread)
// ---------------------------------------------------------------------------
__global__ __launch_bounds__(256) void vprep_kernel(const float* __restrict__ v) {
    const size_t i8 = (size_t)blockIdx.x * 256 + threadIdx.x;
    const float4 v0 = ((const float4*)v)[i8 * 2];
    const float4 v1 = ((const float4*)v)[i8 * 2 + 1];
    uint4 o;
    __half2 h;
    h = __floats2half2_rn(v0.x, v0.y); o.x = *(unsigned*)&h;
    h = __floats2half2_rn(v0.z, v0.w); o.y = *(unsigned*)&h;
    h = __floats2half2_rn(v1.x, v1.y); o.z = *(unsigned*)&h;
    h = __floats2half2_rn(v1.z, v1.w); o.w = *(unsigned*)&h;
    ((uint4*)g_vh)[i8] = o;
}

// ---------------------------------------------------------------------------
// Kernel P1: W2 -> transposed fp16 (tiled transpose)
// ---------------------------------------------------------------------------
__global__ __launch_bounds__(256) void w2t_prep_kernel(const float* __restrict__ W2) {
    __shared__ float tile[32][33];
    const int d0 = blockIdx.x * 32, u0 = blockIdx.y * 32;
    const int tx = threadIdx.x & 31, ty = threadIdx.x >> 5;   // 32 x 8
#pragma unroll
    for (int i = 0; i < 4; i++)
        tile[ty * 4 + i][tx] = W2[(size_t)(d0 + ty * 4 + i) * U_SZ + u0 + tx];
    __syncthreads();
#pragma unroll
    for (int i = 0; i < 4; i++) {
        const int u = u0 + ty * 4 + i;
        g_W2t[(size_t)u * D_SZ + d0 + tx] = __float2half_rn(tile[tx][ty * 4 + i]);
    }
}

// ---------------------------------------------------------------------------
// Kernel 1: A[b,u] = q@W1 + b1 + b2   (fp32, exact)
// ---------------------------------------------------------------------------
__global__ __launch_bounds__(256) void qproj_kernel(
    const float* __restrict__ query, const float* __restrict__ W1,
    const float* __restrict__ b1, const float* __restrict__ b2) {
    __shared__ float qs[D_SZ];
    const int b = blockIdx.y;
    const int u = blockIdx.x * 256 + threadIdx.x;
#pragma unroll
    for (int i = 0; i < 4; i++)
        qs[threadIdx.x + i * 256] = query[b * D_SZ + threadIdx.x + i * 256];
    __syncthreads();
    float a0 = 0.f, a1 = 0.f, a2 = 0.f, a3 = 0.f;
#pragma unroll 4
    for (int d = 0; d < D_SZ; d += 4) {
        a0 += qs[d + 0] * W1[(size_t)(d + 0) * U_SZ + u];
        a1 += qs[d + 1] * W1[(size_t)(d + 1) * U_SZ + u];
        a2 += qs[d + 2] * W1[(size_t)(d + 2) * U_SZ + u];
        a3 += qs[d + 3] * W1[(size_t)(d + 3) * U_SZ + u];
    }
    g_A[b * U_SZ + u] = b1[u] + b2[u] + ((a0 + a1) + (a2 + a3));
}

// ---------------------------------------------------------------------------
// Kernel 2 (dominant): fp16 mma.sync GEMM + tanh + Wv partial reduce
// Grid (x=pass 16, y=t-tile 16, z=b 32): pass-fastest order -> A tile served
// from L2 (verified R10). CTA: 128 t x 64 u x K=1024; 256 threads = 8 warps
// (4m x 2n), warp tile 32x32 -> 32 accum regs -> fits 3 CTAs/SM (73.5 KB smem,
// <=84 regs via launch_bounds). 16 K-chunks of 64, 3-stage cp.async pipeline,
// one __syncthreads per chunk.
// ---------------------------------------------------------------------------
#define TT 128
#define UC 64
#define KC 64
#define NCHUNK 16
#define OFF_B 16384                        // A = 128 rows x 128 B
#define STAGE 24576                        // A 16KB + B 8KB
#define EX (3 * STAGE)                     // 73728
#define SMEM_BYTES (EX + 512 + 1024)       // + sAWv[64] + sred[2][128]

__device__ __forceinline__ void issue_chunk(
    uint32_t sbase, const __half* Abase, const __half* Bbase, int kc, int tid) {
    // A: 128 rows x 64 halves (4 x 16B per thread)
#pragma unroll
    for (int i = 0; i < 4; i++) {
        const int idx = i * 256 + tid;
        const int r = idx >> 3;
        const int c8 = idx & 7;
        const uint32_t sw = (uint32_t)(c8 * 16) ^ (((uint32_t)r & 7u) << 4);
        CP16(sbase + r * 128 + sw, Abase + (size_t)r * D_SZ + kc + c8 * 8);
    }
    // B: 64 rows x 64 halves (2 x 16B per thread)
#pragma unroll
    for (int i = 0; i < 2; i++) {
        const int idx = i * 256 + tid;
        const int r = idx >> 3;
        const int c8 = idx & 7;
        const uint32_t sw = (uint32_t)(c8 * 16) ^ (((uint32_t)r & 7u) << 4);
        CP16(sbase + OFF_B + r * 128 + sw, Bbase + (size_t)r * D_SZ + kc + c8 * 8);
    }
}

__global__ __launch_bounds__(256, 3) void score_mma_kernel(
    const float* __restrict__ Wv) {
    extern __shared__ char sm[];
    const uint32_t base = smem_u32(sm);
    float2* sAWv = (float2*)(sm + EX);
    float(*sred)[TT] = (float(*)[TT])(sm + EX + 512);

    const int tid = threadIdx.x;
    const int wid = tid >> 5;
    const int lane = tid & 31;
    const int p = blockIdx.x;          // u-pass (fastest -> L2 reuse of A)
    const int t0 = blockIdx.y * TT;
    const int b = blockIdx.z;
    const int u0 = p * UC;

    const int m0 = (wid & 3) * 32;
    const int wn = wid >> 2;
    const int n0 = wn * 32;

    const __half* Abase = g_vh + ((size_t)b * T_SZ + t0) * D_SZ;
    const __half* Bbase = g_W2t + (size_t)u0 * D_SZ;

    if (tid < UC)
        sAWv[tid] = make_float2(g_A[b * U_SZ + u0 + tid], Wv[u0 + tid]);

    // ldmatrix per-lane address components (mapping verified in R4/R5)
    const int mat = lane >> 3, mr = lane & 7;
    const int rowA = m0 + (mat & 1) * 8 + mr;
    const uint32_t aBase0 = rowA * 128, aBase1 = aBase0 + 16 * 128;
    const uint32_t aXor = ((uint32_t)rowA & 7u) << 4;
    const uint32_t aCb = (mat >> 1) * 16;
    const int rowB0 = n0 + (mat >> 1) * 8 + mr;
    const uint32_t bXor = ((uint32_t)rowB0 & 7u) << 4;
    const uint32_t bCb = (mat & 1) * 16;
    uint32_t bBase[2];
#pragma unroll
    for (int ntp = 0; ntp < 2; ntp++)
        bBase[ntp] = OFF_B + (rowB0 + ntp * 16) * 128;

    const int fr = lane >> 2;
    const int fc = (lane & 3) * 2;

    float acc[2][4][4];
#pragma unroll
    for (int mt = 0; mt < 2; mt++)
#pragma unroll
        for (int nt = 0; nt < 4; nt++)
#pragma unroll
            for (int ci = 0; ci < 4; ci++) acc[mt][nt][ci] = 0.f;

    // prologue: chunks 0, 1
    issue_chunk(base, Abase, Bbase, 0, tid);
    CP_COMMIT();
    issue_chunk(base + STAGE, Abase, Bbase, KC, tid);
    CP_COMMIT();

#pragma unroll 1
    for (int c = 0; c < NCHUNK; c++) {
        if (c < NCHUNK - 1) { CP_WAIT(1); } else { CP_WAIT(0); }
        __syncthreads();   // chunk c visible; stage (c+2)%3 free to refill

        if (c + 2 < NCHUNK) {
            issue_chunk(base + ((c + 2) % 3) * STAGE, Abase, Bbase,
                        (c + 2) * KC, tid);
            CP_COMMIT();
        }

        const uint32_t st = base + (c % 3) * STAGE;
#pragma unroll
        for (int ks = 0; ks < 4; ks++) {
            uint32_t ah[2][4];
            const uint32_t ac = ((uint32_t)(ks * 32) + aCb) ^ aXor;
            LDSM4(ah[0][0], ah[0][1], ah[0][2], ah[0][3], st + aBase0 + ac);
            LDSM4(ah[1][0], ah[1][1], ah[1][2], ah[1][3], st + aBase1 + ac);
            const uint32_t bc = ((uint32_t)(ks * 32) + bCb) ^ bXor;
#pragma unroll
            for (int ntp = 0; ntp < 2; ntp++) {
                uint32_t b0, b1, b2, b3;
                LDSM4(b0, b1, b2, b3, st + bBase[ntp] + bc);
                MMA_F16(acc[0][ntp * 2 + 0], ah[0], b0, b1);
                MMA_F16(acc[0][ntp * 2 + 1], ah[0], b2, b3);
                MMA_F16(acc[1][ntp * 2 + 0], ah[1], b0, b1);
                MMA_F16(acc[1][ntp * 2 + 1], ah[1], b2, b3);
            }
        }
        // no trailing sync: next overwrite of stage c%3 (chunk c+3) is gated
        // by the top-of-iteration sync of iter c+1.
    }

    // ---- epilogue: s = sum_u Wv[u] * tanh(D + Aq[u]) over this pass's 64 u
    float s_part[4];
#pragma unroll
    for (int mt = 0; mt < 2; mt++)
#pragma unroll
        for (int h2 = 0; h2 < 2; h2++) {
            float a = 0.f;
#pragma unroll
            for (int nt = 0; nt < 4; nt++) {
                const int cl = n0 + nt * 8 + fc;
                const float2 aw0 = sAWv[cl];
                const float2 aw1 = sAWv[cl + 1];
                a += aw0.y * tanh_approx(acc[mt][nt][h2 * 2 + 0] + aw0.x);
                a += aw1.y * tanh_approx(acc[mt][nt][h2 * 2 + 1] + aw1.x);
            }
            s_part[mt * 2 + h2] = a;
        }

    // reduce quads (lanes sharing a row), then across the 2 n-warps
#pragma unroll
    for (int sp = 0; sp < 4; sp++) {
        float v = s_part[sp];
        v += __shfl_xor_sync(0xffffffffu, v, 1);
        v += __shfl_xor_sync(0xffffffffu, v, 2);
        if ((lane & 3) == 0) sred[wn][m0 + sp * 8 + fr] = v;
    }
    __syncthreads();
    if (tid < TT)
        g_spart[((size_t)p * B_SZ + b) * T_SZ + t0 + tid] =
            sred[0][tid] + sred[1][tid];
}

// ---------------------------------------------------------------------------
// Kernel 3: sum pass-partials + softmax over T per batch -> attention weights
// ---------------------------------------------------------------------------
__global__ __launch_bounds__(256) void softmax_kernel(
    float* __restrict__ wout, const float* __restrict__ bvp) {
    __shared__ float red[256];
    __shared__ float sc[T_SZ];
    const int b = blockIdx.x;
    const int tid = threadIdx.x;
    float* w = wout + b * T_SZ;
    const float bv0 = bvp[0];

    float m = -3.4e38f;
    for (int t = tid; t < T_SZ; t += 256) {
        float s = bv0;
#pragma unroll
        for (int p = 0; p < NPASS; p++)
            s += g_spart[((size_t)p * B_SZ + b) * T_SZ + t];
        sc[t] = s;
        m = fmaxf(m, s);
    }
    red[tid] = m;
    __syncthreads();
    for (int o = 128; o > 0; o >>= 1) {
        if (tid < o) red[tid] = fmaxf(red[tid], red[tid + o]);
        __syncthreads();
    }
    const float mx = red[0];
    __syncthreads();

    float sum = 0.f;
    for (int t = tid; t < T_SZ; t += 256) {
        float e = __expf(sc[t] - mx);
        w[t] = e;
        sum += e;
    }
    red[tid] = sum;
    __syncthreads();
    for (int o = 128; o > 0; o >>= 1) {
        if (tid < o) red[tid] += red[tid + o];
        __syncthreads();
    }
    const float inv = 1.0f / red[0];
    for (int t = tid; t < T_SZ; t += 256) w[t] *= inv;
}

// ---------------------------------------------------------------------------
// Kernel 4/5: context = sum_t w*values (fp16 values, half2, 8-way t-split)
// ---------------------------------------------------------------------------
__global__ __launch_bounds__(256) void context_part_kernel(
    const float* __restrict__ w) {
    __shared__ float wsh[256];
    const int b = blockIdx.y;
    const int z = blockIdx.z;
    const int d2 = blockIdx.x * 256 + threadIdx.x;   // half2 index (0..511)
    const int t0 = z * (T_SZ / CSPLIT);
    if (threadIdx.x < 256) wsh[threadIdx.x] = w[b * T_SZ + t0 + threadIdx.x];
    __syncthreads();
    const __half2* vb = (const __half2*)(g_vh + ((size_t)b * T_SZ + t0) * D_SZ) + d2;
    float2 a0 = {0.f, 0.f}, a1 = {0.f, 0.f};
#pragma unroll 4
    for (int t = 0; t < T_SZ / CSPLIT; t += 2) {
        const float2 v0 = __half22float2(vb[(size_t)(t + 0) * (D_SZ / 2)]);
        const float2 v1 = __half22float2(vb[(size_t)(t + 1) * (D_SZ / 2)]);
        const float w0 = wsh[t + 0], w1 = wsh[t + 1];
        a0.x += w0 * v0.x; a0.y += w0 * v0.y;
        a1.x += w1 * v1.x; a1.y += w1 * v1.y;
    }
    float2 r;
    r.x = a0.x + a1.x;
    r.y = a0.y + a1.y;
    ((float2*)(g_cpart + ((size_t)z * B_SZ + b) * D_SZ))[d2] = r;
}

__global__ void context_reduce_kernel(float* __restrict__ out) {
    const int b = blockIdx.x;
    const int d = threadIdx.x;
    float s = 0.f;
#pragma unroll
    for (int z = 0; z < CSPLIT; z++)
        s += g_cpart[((size_t)z * B_SZ + b) * D_SZ + d];
    out[b * D_SZ + d] = s;
}

// ---------------------------------------------------------------------------
extern "C" void kernel_launch(void* const* d_in, const int* in_sizes, int n_in,
                              void* d_out, int out_size) {
    const float* query  = (const float*)d_in[0];
    const float* values = (const float*)d_in[1];
    const float* W1     = (const float*)d_in[2];
    const float* b1     = (const float*)d_in[3];
    const float* W2     = (const float*)d_in[4];
    const float* b2     = (const float*)d_in[5];
    const float* Wv     = (const float*)d_in[6];
    const float* bv     = (const float*)d_in[7];

    float* out = (float*)d_out;
    float* ctx_out = out;                  // [B, D]
    float* w_out   = out + B_SZ * D_SZ;    // [B, T, 1]

    static int smem_set = 0;
    if (!smem_set) {
        cudaFuncSetAttribute(score_mma_kernel,
                             cudaFuncAttributeMaxDynamicSharedMemorySize, SMEM_BYTES);
        smem_set = 1;
    }

    // launch index 3 = score_mma_kernel (ncu captures index 3 in this harness)
    vprep_kernel<<<32768, 256>>>(values);                            // 0
    w2t_prep_kernel<<<dim3(D_SZ / 32, U_SZ / 32), 256>>>(W2);        // 1
    qproj_kernel<<<dim3(4, B_SZ), 256>>>(query, W1, b1, b2);         // 2
    score_mma_kernel<<<dim3(NPASS, T_SZ / TT, B_SZ), 256, SMEM_BYTES>>>(Wv); // 3
    softmax_kernel<<<B_SZ, 256>>>(w_out, bv);                        // 4
    context_part_kernel<<<dim3(2, B_SZ, CSPLIT), 256>>>(w_out);      // 5
    context_reduce_kernel<<<B_SZ, 1024>>>(ctx_out);                  // 6
}

// round 16
// speedup vs baseline: 1.5708x; 1.5708x over previous
#include <cuda_runtime.h>
#include <cuda_fp16.h>
#include <cstdint>
#include <math.h>

#define B_SZ 32
#define T_SZ 2048
#define D_SZ 1024
#define U_SZ 1024
#define NPASS 8
#define CSPLIT 8

typedef unsigned long long u64;

// ---------------- static device scratch (no runtime allocation) -------------
__device__ float g_A[B_SZ * U_SZ];               // q@W1 + b1 + b2
__device__ float g_spart[NPASS * B_SZ * T_SZ];   // per-pass partial scores
__device__ float g_cpart[CSPLIT * B_SZ * D_SZ];  // context partials
__device__ __half g_W2t[U_SZ * D_SZ];            // W2^T fp16 [u][d]
__device__ __half g_vh[67108864];                // values as fp16 (B*T*D)

// ---------------- PTX helpers ----------------------------------------------
__device__ __forceinline__ uint32_t smem_u32(const void* p) {
    uint32_t a;
    asm("{ .reg .u64 t; cvta.to.shared.u64 t, %1; cvt.u32.u64 %0, t; }"
        : "=r"(a) : "l"(p));
    return a;
}
__device__ __forceinline__ float tanh_approx(float x) {
    float y;
    asm("tanh.approx.f32 %0, %1;" : "=f"(y) : "f"(x));
    return y;
}
#define CP16(s, g) \
    asm volatile("cp.async.cg.shared.global [%0], [%1], 16;" :: "r"(s), "l"(g))
#define CP_COMMIT() asm volatile("cp.async.commit_group;" ::: "memory")
#define CP_WAIT(n) asm volatile("cp.async.wait_group %0;" :: "n"(n) : "memory")
#define LDSM4(R0, R1, R2, R3, A) \
    asm volatile("ldmatrix.sync.aligned.m8n8.x4.shared.b16 {%0,%1,%2,%3}, [%4];" \
                 : "=r"(R0), "=r"(R1), "=r"(R2), "=r"(R3) : "r"(A))
#define MMA_F16(d, a, b0, b1)                                               \
    asm volatile(                                                           \
        "mma.sync.aligned.m16n8k16.row.col.f32.f16.f16.f32 "                \
        "{%0,%1,%2,%3}, {%4,%5,%6,%7}, {%8,%9}, {%0,%1,%2,%3};"             \
        : "+f"((d)[0]), "+f"((d)[1]), "+f"((d)[2]), "+f"((d)[3])            \
        : "r"((a)[0]), "r"((a)[1]), "r"((a)[2]), "r"((a)[3]),               \
          "r"(b0), "r"(b1))

// ---------------------------------------------------------------------------
// Kernel P (fused prep): one launch, block-range dispatch.
//   blocks [0, 32768)          : values fp32 -> fp16
//   blocks [32768, 33792)      : W2 -> transposed fp16 (32x32 tiles)
//   blocks [33792, 33920)      : A[b,u] = q@W1 + b1 + b2
// vprep blocks launch first (DRAM-bound); the small compute blocks fill its
// tail wave instead of costing two extra serialized launches.
// ---------------------------------------------------------------------------
#define VPREP_BLKS 32768
#define W2T_BLKS   1024
#define PREP_BLKS  (VPREP_BLKS + W2T_BLKS + 128)

__global__ __launch_bounds__(256) void prep_kernel(
    const float* __restrict__ v, const float* __restrict__ W2,
    const float* __restrict__ query, const float* __restrict__ W1,
    const float* __restrict__ b1, const float* __restrict__ b2) {
    const int bx = blockIdx.x;

    if (bx < VPREP_BLKS) {
        // ---- values fp32 -> fp16 (one uint4 = 8 halves per thread)
        const size_t i8 = (size_t)bx * 256 + threadIdx.x;
        const float4 v0 = ((const float4*)v)[i8 * 2];
        const float4 v1 = ((const float4*)v)[i8 * 2 + 1];
        uint4 o;
        __half2 h;
        h = __floats2half2_rn(v0.x, v0.y); o.x = *(unsigned*)&h;
        h = __floats2half2_rn(v0.z, v0.w); o.y = *(unsigned*)&h;
        h = __floats2half2_rn(v1.x, v1.y); o.z = *(unsigned*)&h;
        h = __floats2half2_rn(v1.z, v1.w); o.w = *(unsigned*)&h;
        ((uint4*)g_vh)[i8] = o;
    } else if (bx < VPREP_BLKS + W2T_BLKS) {
        // ---- W2 -> transposed fp16 (tiled transpose)
        __shared__ float tile[32][33];
        const int r = bx - VPREP_BLKS;
        const int d0 = (r & 31) * 32, u0 = (r >> 5) * 32;
        const int tx = threadIdx.x & 31, ty = threadIdx.x >> 5;   // 32 x 8
#pragma unroll
        for (int i = 0; i < 4; i++)
            tile[ty * 4 + i][tx] = W2[(size_t)(d0 + ty * 4 + i) * U_SZ + u0 + tx];
        __syncthreads();
#pragma unroll
        for (int i = 0; i < 4; i++) {
            const int u = u0 + ty * 4 + i;
            g_W2t[(size_t)u * D_SZ + d0 + tx] =
                __float2half_rn(tile[tx][ty * 4 + i]);
        }
    } else {
        // ---- qproj: A[b,u] = q@W1 + b1 + b2 (fp32, exact)
        __shared__ float qs[D_SZ];
        const int r = bx - VPREP_BLKS - W2T_BLKS;
        const int b = r >> 2;
        const int u = (r & 3) * 256 + threadIdx.x;
#pragma unroll
        for (int i = 0; i < 4; i++)
            qs[threadIdx.x + i * 256] = query[b * D_SZ + threadIdx.x + i * 256];
        __syncthreads();
        float a0 = 0.f, a1 = 0.f, a2 = 0.f, a3 = 0.f;
#pragma unroll 4
        for (int d = 0; d < D_SZ; d += 4) {
            a0 += qs[d + 0] * W1[(size_t)(d + 0) * U_SZ + u];
            a1 += qs[d + 1] * W1[(size_t)(d + 1) * U_SZ + u];
            a2 += qs[d + 2] * W1[(size_t)(d + 2) * U_SZ + u];
            a3 += qs[d + 3] * W1[(size_t)(d + 3) * U_SZ + u];
        }
        g_A[b * U_SZ + u] = b1[u] + b2[u] + ((a0 + a1) + (a2 + a3));
    }
}

// ---------------------------------------------------------------------------
// Kernel 2 (dominant, R12-identical): fp16 mma.sync GEMM + tanh + Wv reduce
// Grid (x=pass 8, y=t-tile 16, z=b 32): pass-fastest order -> A tile served
// from L2 (verified R10: DRAM 43.8% -> 5.8%).
// CTA: 128 t x 128 u x K=1024; 256 threads = 8 warps (4m x 2n), warp 32x64.
// 16 K-chunks of 64, 3-stage cp.async pipeline, ONE __syncthreads per chunk.
// ---------------------------------------------------------------------------
#define TT 128
#define UC 128
#define KC 64
#define NCHUNK 16
#define OFF_B 16384
#define STAGE 32768
#define EX (3 * STAGE)                    // 98304
#define SMEM_BYTES (EX + 1024 + 1024)     // + sAWv[128] + sred[2][128]

__device__ __forceinline__ void issue_chunk(
    uint32_t sbase, const __half* Abase, const __half* Bbase, int kc, int tid) {
#pragma unroll
    for (int i = 0; i < 4; i++) {
        const int idx = i * 256 + tid;
        const int r = idx >> 3;
        const int c8 = idx & 7;
        const uint32_t sw = (uint32_t)(c8 * 16) ^ (((uint32_t)r & 7u) << 4);
        CP16(sbase + r * 128 + sw, Abase + (size_t)r * D_SZ + kc + c8 * 8);
        CP16(sbase + OFF_B + r * 128 + sw, Bbase + (size_t)r * D_SZ + kc + c8 * 8);
    }
}

__global__ __launch_bounds__(256, 2) void score_mma_kernel(
    const float* __restrict__ Wv) {
    extern __shared__ char sm[];
    const uint32_t base = smem_u32(sm);
    float2* sAWv = (float2*)(sm + EX);
    float(*sred)[TT] = (float(*)[TT])(sm + EX + 1024);

    const int tid = threadIdx.x;
    const int wid = tid >> 5;
    const int lane = tid & 31;
    const int p = blockIdx.x;          // u-pass (fastest -> L2 reuse of A)
    const int t0 = blockIdx.y * TT;
    const int b = blockIdx.z;
    const int u0 = p * UC;

    const int m0 = (wid & 3) * 32;
    const int wn = wid >> 2;
    const int n0 = wn * 64;

    const __half* Abase = g_vh + ((size_t)b * T_SZ + t0) * D_SZ;
    const __half* Bbase = g_W2t + (size_t)u0 * D_SZ;

    if (tid < UC)
        sAWv[tid] = make_float2(g_A[b * U_SZ + u0 + tid], Wv[u0 + tid]);

    // ldmatrix per-lane address components (mapping verified in R4/R5)
    const int mat = lane >> 3, mr = lane & 7;
    const int rowA = m0 + (mat & 1) * 8 + mr;
    const uint32_t aBase0 = rowA * 128, aBase1 = aBase0 + 16 * 128;
    const uint32_t aXor = ((uint32_t)rowA & 7u) << 4;
    const uint32_t aCb = (mat >> 1) * 16;
    const int rowB0 = n0 + (mat >> 1) * 8 + mr;
    const uint32_t bXor = ((uint32_t)rowB0 & 7u) << 4;
    const uint32_t bCb = (mat & 1) * 16;
    uint32_t bBase[4];
#pragma unroll
    for (int ntp = 0; ntp < 4; ntp++)
        bBase[ntp] = OFF_B + (rowB0 + ntp * 16) * 128;

    const int fr = lane >> 2;
    const int fc = (lane & 3) * 2;

    float acc[2][8][4];
#pragma unroll
    for (int mt = 0; mt < 2; mt++)
#pragma unroll
        for (int nt = 0; nt < 8; nt++)
#pragma unroll
            for (int ci = 0; ci < 4; ci++) acc[mt][nt][ci] = 0.f;

    // prologue: chunks 0, 1
    issue_chunk(base, Abase, Bbase, 0, tid);
    CP_COMMIT();
    issue_chunk(base + STAGE, Abase, Bbase, KC, tid);
    CP_COMMIT();

#pragma unroll 1
    for (int c = 0; c < NCHUNK; c++) {
        if (c < NCHUNK - 1) { CP_WAIT(1); } else { CP_WAIT(0); }
        __syncthreads();   // chunk c visible; stage (c+2)%3 free to refill

        if (c + 2 < NCHUNK) {
            issue_chunk(base + ((c + 2) % 3) * STAGE, Abase, Bbase,
                        (c + 2) * KC, tid);
            CP_COMMIT();
        }

        const uint32_t st = base + (c % 3) * STAGE;
#pragma unroll
        for (int ks = 0; ks < 4; ks++) {
            uint32_t ah[2][4];
            const uint32_t ac = ((uint32_t)(ks * 32) + aCb) ^ aXor;
            LDSM4(ah[0][0], ah[0][1], ah[0][2], ah[0][3], st + aBase0 + ac);
            LDSM4(ah[1][0], ah[1][1], ah[1][2], ah[1][3], st + aBase1 + ac);
            const uint32_t bc = ((uint32_t)(ks * 32) + bCb) ^ bXor;
#pragma unroll
            for (int ntp = 0; ntp < 4; ntp++) {
                uint32_t b0, b1, b2, b3;
                LDSM4(b0, b1, b2, b3, st + bBase[ntp] + bc);
                MMA_F16(acc[0][ntp * 2 + 0], ah[0], b0, b1);
                MMA_F16(acc[0][ntp * 2 + 1], ah[0], b2, b3);
                MMA_F16(acc[1][ntp * 2 + 0], ah[1], b0, b1);
                MMA_F16(acc[1][ntp * 2 + 1], ah[1], b2, b3);
            }
        }
        // no trailing sync: next overwrite of stage c%3 (chunk c+3) is gated
        // by the top-of-iteration sync of iter c+1.
    }

    // ---- epilogue: s = sum_u Wv[u] * tanh(D + Aq[u]) over this pass's 128 u
    float s_part[4];
#pragma unroll
    for (int mt = 0; mt < 2; mt++)
#pragma unroll
        for (int h2 = 0; h2 < 2; h2++) {
            float a = 0.f;
#pragma unroll
            for (int nt = 0; nt < 8; nt++) {
                const int cl = n0 + nt * 8 + fc;
                const float2 aw0 = sAWv[cl];
                const float2 aw1 = sAWv[cl + 1];
                a += aw0.y * tanh_approx(acc[mt][nt][h2 * 2 + 0] + aw0.x);
                a += aw1.y * tanh_approx(acc[mt][nt][h2 * 2 + 1] + aw1.x);
            }
            s_part[mt * 2 + h2] = a;
        }

    // reduce quads (lanes sharing a row), then across the 2 n-warps
#pragma unroll
    for (int sp = 0; sp < 4; sp++) {
        float v = s_part[sp];
        v += __shfl_xor_sync(0xffffffffu, v, 1);
        v += __shfl_xor_sync(0xffffffffu, v, 2);
        if ((lane & 3) == 0) sred[wn][m0 + sp * 8 + fr] = v;
    }
    __syncthreads();
    if (tid < TT)
        g_spart[((size_t)p * B_SZ + b) * T_SZ + t0 + tid] =
            sred[0][tid] + sred[1][tid];
}

// ---------------------------------------------------------------------------
// Kernel 3: sum pass-partials + softmax over T per batch -> attention weights
// ---------------------------------------------------------------------------
__global__ __launch_bounds__(256) void softmax_kernel(
    float* __restrict__ wout, const float* __restrict__ bvp) {
    __shared__ float red[256];
    __shared__ float sc[T_SZ];
    const int b = blockIdx.x;
    const int tid = threadIdx.x;
    float* w = wout + b * T_SZ;
    const float bv0 = bvp[0];

    float m = -3.4e38f;
    for (int t = tid; t < T_SZ; t += 256) {
        float s = bv0;
#pragma unroll
        for (int p = 0; p < NPASS; p++)
            s += g_spart[((size_t)p * B_SZ + b) * T_SZ + t];
        sc[t] = s;
        m = fmaxf(m, s);
    }
    red[tid] = m;
    __syncthreads();
    for (int o = 128; o > 0; o >>= 1) {
        if (tid < o) red[tid] = fmaxf(red[tid], red[tid + o]);
        __syncthreads();
    }
    const float mx = red[0];
    __syncthreads();

    float sum = 0.f;
    for (int t = tid; t < T_SZ; t += 256) {
        float e = __expf(sc[t] - mx);
        w[t] = e;
        sum += e;
    }
    red[tid] = sum;
    __syncthreads();
    for (int o = 128; o > 0; o >>= 1) {
        if (tid < o) red[tid] += red[tid + o];
        __syncthreads();
    }
    const float inv = 1.0f / red[0];
    for (int t = tid; t < T_SZ; t += 256) w[t] *= inv;
}

// ---------------------------------------------------------------------------
// Kernel 4/5: context = sum_t w*values (fp16 values, half2, 8-way t-split)
// ---------------------------------------------------------------------------
__global__ __launch_bounds__(256) void context_part_kernel(
    const float* __restrict__ w) {
    __shared__ float wsh[256];
    const int b = blockIdx.y;
    const int z = blockIdx.z;
    const int d2 = blockIdx.x * 256 + threadIdx.x;   // half2 index (0..511)
    const int t0 = z * (T_SZ / CSPLIT);
    if (threadIdx.x < 256) wsh[threadIdx.x] = w[b * T_SZ + t0 + threadIdx.x];
    __syncthreads();
    const __half2* vb = (const __half2*)(g_vh + ((size_t)b * T_SZ + t0) * D_SZ) + d2;
    float2 a0 = {0.f, 0.f}, a1 = {0.f, 0.f};
#pragma unroll 4
    for (int t = 0; t < T_SZ / CSPLIT; t += 2) {
        const float2 v0 = __half22float2(vb[(size_t)(t + 0) * (D_SZ / 2)]);
        const float2 v1 = __half22float2(vb[(size_t)(t + 1) * (D_SZ / 2)]);
        const float w0 = wsh[t + 0], w1 = wsh[t + 1];
        a0.x += w0 * v0.x; a0.y += w0 * v0.y;
        a1.x += w1 * v1.x; a1.y += w1 * v1.y;
    }
    float2 r;
    r.x = a0.x + a1.x;
    r.y = a0.y + a1.y;
    ((float2*)(g_cpart + ((size_t)z * B_SZ + b) * D_SZ))[d2] = r;
}

__global__ void context_reduce_kernel(float* __restrict__ out) {
    const int b = blockIdx.x;
    const int d = threadIdx.x;
    float s = 0.f;
#pragma unroll
    for (int z = 0; z < CSPLIT; z++)
        s += g_cpart[((size_t)z * B_SZ + b) * D_SZ + d];
    out[b * D_SZ + d] = s;
}

// ---------------------------------------------------------------------------
extern "C" void kernel_launch(void* const* d_in, const int* in_sizes, int n_in,
                              void* d_out, int out_size) {
    const float* query  = (const float*)d_in[0];
    const float* values = (const float*)d_in[1];
    const float* W1     = (const float*)d_in[2];
    const float* b1     = (const float*)d_in[3];
    const float* W2     = (const float*)d_in[4];
    const float* b2     = (const float*)d_in[5];
    const float* Wv     = (const float*)d_in[6];
    const float* bv     = (const float*)d_in[7];

    float* out = (float*)d_out;
    float* ctx_out = out;                  // [B, D]
    float* w_out   = out + B_SZ * D_SZ;    // [B, T, 1]

    static int smem_set = 0;
    if (!smem_set) {
        cudaFuncSetAttribute(score_mma_kernel,
                             cudaFuncAttributeMaxDynamicSharedMemorySize, SMEM_BYTES);
        smem_set = 1;
    }

    // launch index 1 = score_mma_kernel
    prep_kernel<<<PREP_BLKS, 256>>>(values, W2, query, W1, b1, b2);  // 0
    score_mma_kernel<<<dim3(NPASS, T_SZ / TT, B_SZ), 256, SMEM_BYTES>>>(Wv); // 1
    softmax_kernel<<<B_SZ, 256>>>(w_out, bv);                        // 2
    context_part_kernel<<<dim3(2, B_SZ, CSPLIT), 256>>>(w_out);      // 3
    context_reduce_kernel<<<B_SZ, 1024>>>(ctx_out);                  // 4
}